// round 2
// baseline (speedup 1.0000x reference)
#include <cuda_runtime.h>

// Problem constants (fixed shapes from reference)
#define BB 16
#define HH 512
#define WW 512
#define H2 1024
#define W2 1024
#define WV (W2 / 4)   // float4 vectors per output row

// Fused: bilinear 2x upsample of mask (2ch) -> x_mask,y_mask;
// fused_c = xm*xl_c + ym*yl_c; out_o = relu(sum_i w[o,i]*fused_i + b_o).
// One thread = 4 consecutive output columns (float4) for all channels.
// R2: streaming cache hints (__ldcs/__stcs) on the one-touch tensors so L2
// ways stay reserved for the reused mask rows.
__global__ void __launch_bounds__(256) fused_upsample_blend_conv_kernel(
    const float* __restrict__ mask,   // (B,2,H,W)
    const float* __restrict__ xl,     // (B,3,H2,W2)
    const float* __restrict__ yl,     // (B,3,H2,W2)
    const float* __restrict__ cw,     // (3,3) row-major 'oi'
    const float* __restrict__ cb,     // (3,)
    float* __restrict__ out)          // (B,3,H2,W2) ++ (B,1,H2,W2) ++ (B,1,H2,W2)
{
    int idx = blockIdx.x * blockDim.x + threadIdx.x;
    int ox4 = idx % WV;              // vector index along width (power of 2 -> shifts)
    int t   = idx / WV;
    int oy  = t % H2;
    int b   = t / H2;
    if (b >= BB) return;

    // ---- vertical bilinear weights (half-pixel centers, 2x upsample) ----
    int ky = oy >> 1;
    int y0, y1; float wy0, wy1;
    if ((oy & 1) == 0) {             // src = ky - 0.25
        y0 = ky - 1; if (y0 < 0) y0 = 0;
        y1 = ky;
        wy0 = 0.25f; wy1 = 0.75f;
    } else {                          // src = ky + 0.25
        y0 = ky;
        y1 = ky + 1; if (y1 > HH - 1) y1 = HH - 1;
        wy0 = 0.75f; wy1 = 0.25f;
    }

    // ---- horizontal: 4 outputs share input cols {m-1, m, m+1, m+2} ----
    int m   = ox4 * 2;                       // 0..510, even
    int cm1 = m - 1; if (cm1 < 0) cm1 = 0;
    int cp1 = m + 1;                         // <= 511 always
    int cp2 = m + 2; if (cp2 > WW - 1) cp2 = WW - 1;

    const size_t mplane = (size_t)HH * WW;
    const float* m0r0 = mask + ((size_t)b * 2 + 0) * mplane + (size_t)y0 * WW;
    const float* m0r1 = mask + ((size_t)b * 2 + 0) * mplane + (size_t)y1 * WW;
    const float* m1r0 = mask + ((size_t)b * 2 + 1) * mplane + (size_t)y0 * WW;
    const float* m1r1 = mask + ((size_t)b * 2 + 1) * mplane + (size_t)y1 * WW;

    // vertical interpolation per input column, per mask channel (cached loads)
    float vx_m1 = wy0 * __ldg(m0r0 + cm1) + wy1 * __ldg(m0r1 + cm1);
    float vx_0  = wy0 * __ldg(m0r0 + m  ) + wy1 * __ldg(m0r1 + m  );
    float vx_1  = wy0 * __ldg(m0r0 + cp1) + wy1 * __ldg(m0r1 + cp1);
    float vx_2  = wy0 * __ldg(m0r0 + cp2) + wy1 * __ldg(m0r1 + cp2);

    float vy_m1 = wy0 * __ldg(m1r0 + cm1) + wy1 * __ldg(m1r1 + cm1);
    float vy_0  = wy0 * __ldg(m1r0 + m  ) + wy1 * __ldg(m1r1 + m  );
    float vy_1  = wy0 * __ldg(m1r0 + cp1) + wy1 * __ldg(m1r1 + cp1);
    float vy_2  = wy0 * __ldg(m1r0 + cp2) + wy1 * __ldg(m1r1 + cp2);

    // horizontal combine -> 4 output columns
    float xm[4], ym[4];
    xm[0] = 0.25f * vx_m1 + 0.75f * vx_0;   // even
    xm[1] = 0.75f * vx_0  + 0.25f * vx_1;   // odd
    xm[2] = 0.25f * vx_0  + 0.75f * vx_1;   // even
    xm[3] = 0.75f * vx_1  + 0.25f * vx_2;   // odd
    ym[0] = 0.25f * vy_m1 + 0.75f * vy_0;
    ym[1] = 0.75f * vy_0  + 0.25f * vy_1;
    ym[2] = 0.25f * vy_0  + 0.75f * vy_1;
    ym[3] = 0.75f * vy_1  + 0.25f * vy_2;

    // ---- load xl/yl (3 channels, float4 each) — streaming / evict-first ----
    const size_t plane = (size_t)H2 * W2;
    const size_t base  = (size_t)b * 3 * plane + (size_t)oy * W2 + (size_t)ox4 * 4;

    float4 xc0 = __ldcs((const float4*)(xl + base));
    float4 xc1 = __ldcs((const float4*)(xl + base + plane));
    float4 xc2 = __ldcs((const float4*)(xl + base + 2 * plane));
    float4 yc0 = __ldcs((const float4*)(yl + base));
    float4 yc1 = __ldcs((const float4*)(yl + base + plane));
    float4 yc2 = __ldcs((const float4*)(yl + base + 2 * plane));

    // fused_c[j] = xm[j]*xl_c[j] + ym[j]*yl_c[j]
    float f0[4] = { xm[0]*xc0.x + ym[0]*yc0.x, xm[1]*xc0.y + ym[1]*yc0.y,
                    xm[2]*xc0.z + ym[2]*yc0.z, xm[3]*xc0.w + ym[3]*yc0.w };
    float f1[4] = { xm[0]*xc1.x + ym[0]*yc1.x, xm[1]*xc1.y + ym[1]*yc1.y,
                    xm[2]*xc1.z + ym[2]*yc1.z, xm[3]*xc1.w + ym[3]*yc1.w };
    float f2[4] = { xm[0]*xc2.x + ym[0]*yc2.x, xm[1]*xc2.y + ym[1]*yc2.y,
                    xm[2]*xc2.z + ym[2]*yc2.z, xm[3]*xc2.w + ym[3]*yc2.w };

    // ---- 3x3 channel mix + bias + relu ----
    float w00 = __ldg(cw + 0), w01 = __ldg(cw + 1), w02 = __ldg(cw + 2);
    float w10 = __ldg(cw + 3), w11 = __ldg(cw + 4), w12 = __ldg(cw + 5);
    float w20 = __ldg(cw + 6), w21 = __ldg(cw + 7), w22 = __ldg(cw + 8);
    float b0 = __ldg(cb + 0), b1 = __ldg(cb + 1), b2 = __ldg(cb + 2);

    float4 o0, o1, o2;
    {
        float r[4];
        #pragma unroll
        for (int j = 0; j < 4; j++) {
            float v = w00 * f0[j] + w01 * f1[j] + w02 * f2[j] + b0;
            r[j] = v > 0.0f ? v : 0.0f;
        }
        o0 = make_float4(r[0], r[1], r[2], r[3]);
        #pragma unroll
        for (int j = 0; j < 4; j++) {
            float v = w10 * f0[j] + w11 * f1[j] + w12 * f2[j] + b1;
            r[j] = v > 0.0f ? v : 0.0f;
        }
        o1 = make_float4(r[0], r[1], r[2], r[3]);
        #pragma unroll
        for (int j = 0; j < 4; j++) {
            float v = w20 * f0[j] + w21 * f1[j] + w22 * f2[j] + b2;
            r[j] = v > 0.0f ? v : 0.0f;
        }
        o2 = make_float4(r[0], r[1], r[2], r[3]);
    }

    // ---- stores — streaming / evict-first (never re-read) ----
    float* out_main = out;                                   // (B,3,H2,W2)
    float* out_xm   = out + (size_t)BB * 3 * plane;          // (B,1,H2,W2)
    float* out_ym   = out_xm + (size_t)BB * plane;           // (B,1,H2,W2)

    __stcs((float4*)(out_main + base),             o0);
    __stcs((float4*)(out_main + base + plane),     o1);
    __stcs((float4*)(out_main + base + 2 * plane), o2);

    size_t mbase = (size_t)b * plane + (size_t)oy * W2 + (size_t)ox4 * 4;
    __stcs((float4*)(out_xm + mbase), make_float4(xm[0], xm[1], xm[2], xm[3]));
    __stcs((float4*)(out_ym + mbase), make_float4(ym[0], ym[1], ym[2], ym[3]));
}

extern "C" void kernel_launch(void* const* d_in, const int* in_sizes, int n_in,
                              void* d_out, int out_size) {
    const float* mask = (const float*)d_in[0];
    const float* xl   = (const float*)d_in[1];
    const float* yl   = (const float*)d_in[2];
    const float* cw   = (const float*)d_in[3];
    const float* cb   = (const float*)d_in[4];
    float* out = (float*)d_out;

    const int total = BB * H2 * WV;          // 4,194,304 threads
    const int threads = 256;
    const int blocks = (total + threads - 1) / threads;
    fused_upsample_blend_conv_kernel<<<blocks, threads>>>(mask, xl, yl, cw, cb, out);
}

// round 3
// speedup vs baseline: 1.0503x; 1.0503x over previous
#include <cuda_runtime.h>

// Problem constants (fixed shapes from reference)
#define BB 16
#define HH 512
#define WW 512
#define H2 1024
#define W2 1024
#define WV (W2 / 4)   // float4 vectors per output row

// Fused: bilinear 2x upsample of mask (2ch) -> x_mask,y_mask;
// fused_c = xm*xl_c + ym*yl_c; out_o = relu(sum_i w[o,i]*fused_i + b_o).
// R3: one thread = 2 output rows (even/odd pair) x 4 columns, all channels.
// Shares mask vertical taps across the row pair, doubles per-thread MLP.
__global__ void __launch_bounds__(256) fused_upsample_blend_conv_kernel(
    const float* __restrict__ mask,   // (B,2,H,W)
    const float* __restrict__ xl,     // (B,3,H2,W2)
    const float* __restrict__ yl,     // (B,3,H2,W2)
    const float* __restrict__ cw,     // (3,3) row-major 'oi'
    const float* __restrict__ cb,     // (3,)
    float* __restrict__ out)          // (B,3,H2,W2) ++ (B,1,H2,W2) ++ (B,1,H2,W2)
{
    int idx = blockIdx.x * blockDim.x + threadIdx.x;
    int ox4 = idx & (WV - 1);        // vector index along width
    int t   = idx >> 8;              // WV = 256
    int k   = t & (HH - 1);          // input row / output row-pair index
    int b   = t >> 9;                // HH = 512
    if (b >= BB) return;

    // Output rows: oy0 = 2k (even, taps rows k-1,k w 0.25/0.75)
    //              oy1 = 2k+1 (odd, taps rows k,k+1 w 0.75/0.25)
    int km1 = k - 1; if (km1 < 0) km1 = 0;
    int kp1 = k + 1; if (kp1 > HH - 1) kp1 = HH - 1;

    // ---- horizontal: 4 outputs share input cols {m-1, m, m+1, m+2} ----
    int m   = ox4 * 2;                       // 0..510, even
    int cm1 = m - 1; if (cm1 < 0) cm1 = 0;
    int cp1 = m + 1;                         // <= 511 always
    int cp2 = m + 2; if (cp2 > WW - 1) cp2 = WW - 1;

    const size_t mplane = (size_t)HH * WW;
    const float* mx = mask + ((size_t)b * 2 + 0) * mplane;
    const float* my = mask + ((size_t)b * 2 + 1) * mplane;
    const float* mx_m = mx + (size_t)km1 * WW;
    const float* mx_0 = mx + (size_t)k   * WW;
    const float* mx_p = mx + (size_t)kp1 * WW;
    const float* my_m = my + (size_t)km1 * WW;
    const float* my_0 = my + (size_t)k   * WW;
    const float* my_p = my + (size_t)kp1 * WW;

    // raw mask samples: 3 rows x 4 cols x 2 channels
    float xA0 = __ldg(mx_m + cm1), xA1 = __ldg(mx_m + m), xA2 = __ldg(mx_m + cp1), xA3 = __ldg(mx_m + cp2);
    float xB0 = __ldg(mx_0 + cm1), xB1 = __ldg(mx_0 + m), xB2 = __ldg(mx_0 + cp1), xB3 = __ldg(mx_0 + cp2);
    float xC0 = __ldg(mx_p + cm1), xC1 = __ldg(mx_p + m), xC2 = __ldg(mx_p + cp1), xC3 = __ldg(mx_p + cp2);
    float yA0 = __ldg(my_m + cm1), yA1 = __ldg(my_m + m), yA2 = __ldg(my_m + cp1), yA3 = __ldg(my_m + cp2);
    float yB0 = __ldg(my_0 + cm1), yB1 = __ldg(my_0 + m), yB2 = __ldg(my_0 + cp1), yB3 = __ldg(my_0 + cp2);
    float yC0 = __ldg(my_p + cm1), yC1 = __ldg(my_p + m), yC2 = __ldg(my_p + cp1), yC3 = __ldg(my_p + cp2);

    // vertical interpolation per input column, for even (e) and odd (o) rows
    float vxe0 = 0.25f*xA0 + 0.75f*xB0, vxe1 = 0.25f*xA1 + 0.75f*xB1;
    float vxe2 = 0.25f*xA2 + 0.75f*xB2, vxe3 = 0.25f*xA3 + 0.75f*xB3;
    float vxo0 = 0.75f*xB0 + 0.25f*xC0, vxo1 = 0.75f*xB1 + 0.25f*xC1;
    float vxo2 = 0.75f*xB2 + 0.25f*xC2, vxo3 = 0.75f*xB3 + 0.25f*xC3;
    float vye0 = 0.25f*yA0 + 0.75f*yB0, vye1 = 0.25f*yA1 + 0.75f*yB1;
    float vye2 = 0.25f*yA2 + 0.75f*yB2, vye3 = 0.25f*yA3 + 0.75f*yB3;
    float vyo0 = 0.75f*yB0 + 0.25f*yC0, vyo1 = 0.75f*yB1 + 0.25f*yC1;
    float vyo2 = 0.75f*yB2 + 0.25f*yC2, vyo3 = 0.75f*yB3 + 0.25f*yC3;

    // horizontal combine -> per-row 4-wide masks
    float xme[4], xmo[4], yme[4], ymo[4];
    xme[0] = 0.25f*vxe0 + 0.75f*vxe1;  xme[1] = 0.75f*vxe1 + 0.25f*vxe2;
    xme[2] = 0.25f*vxe1 + 0.75f*vxe2;  xme[3] = 0.75f*vxe2 + 0.25f*vxe3;
    xmo[0] = 0.25f*vxo0 + 0.75f*vxo1;  xmo[1] = 0.75f*vxo1 + 0.25f*vxo2;
    xmo[2] = 0.25f*vxo1 + 0.75f*vxo2;  xmo[3] = 0.75f*vxo2 + 0.25f*vxo3;
    yme[0] = 0.25f*vye0 + 0.75f*vye1;  yme[1] = 0.75f*vye1 + 0.25f*vye2;
    yme[2] = 0.25f*vye1 + 0.75f*vye2;  yme[3] = 0.75f*vye2 + 0.25f*vye3;
    ymo[0] = 0.25f*vyo0 + 0.75f*vyo1;  ymo[1] = 0.75f*vyo1 + 0.25f*vyo2;
    ymo[2] = 0.25f*vyo1 + 0.75f*vyo2;  ymo[3] = 0.75f*vyo2 + 0.25f*vyo3;

    // ---- load xl/yl: 2 rows x 3 channels x 2 tensors = 12 float4 ----
    const size_t plane = (size_t)H2 * W2;
    const int oy0 = 2 * k;
    const size_t base0 = (size_t)b * 3 * plane + (size_t)oy0 * W2 + (size_t)ox4 * 4;
    const size_t base1 = base0 + W2;   // odd row

    float4 xe0 = *(const float4*)(xl + base0);
    float4 xe1 = *(const float4*)(xl + base0 + plane);
    float4 xe2 = *(const float4*)(xl + base0 + 2 * plane);
    float4 xo0 = *(const float4*)(xl + base1);
    float4 xo1 = *(const float4*)(xl + base1 + plane);
    float4 xo2 = *(const float4*)(xl + base1 + 2 * plane);
    float4 ye0 = *(const float4*)(yl + base0);
    float4 ye1 = *(const float4*)(yl + base0 + plane);
    float4 ye2 = *(const float4*)(yl + base0 + 2 * plane);
    float4 yo0 = *(const float4*)(yl + base1);
    float4 yo1 = *(const float4*)(yl + base1 + plane);
    float4 yo2 = *(const float4*)(yl + base1 + 2 * plane);

    // conv weights / bias
    float w00 = __ldg(cw + 0), w01 = __ldg(cw + 1), w02 = __ldg(cw + 2);
    float w10 = __ldg(cw + 3), w11 = __ldg(cw + 4), w12 = __ldg(cw + 5);
    float w20 = __ldg(cw + 6), w21 = __ldg(cw + 7), w22 = __ldg(cw + 8);
    float b0 = __ldg(cb + 0), b1 = __ldg(cb + 1), b2 = __ldg(cb + 2);

    float* out_main = out;                                   // (B,3,H2,W2)
    float* out_xm   = out + (size_t)BB * 3 * plane;          // (B,1,H2,W2)
    float* out_ym   = out_xm + (size_t)BB * plane;           // (B,1,H2,W2)

    // ---- per-row: blend, channel-mix, relu, store ----
    #pragma unroll
    for (int r = 0; r < 2; r++) {
        const float* xm = r ? xmo : xme;
        const float* ym = r ? ymo : yme;
        float4 c0 = r ? xo0 : xe0, c1 = r ? xo1 : xe1, c2 = r ? xo2 : xe2;
        float4 d0 = r ? yo0 : ye0, d1 = r ? yo1 : ye1, d2 = r ? yo2 : ye2;
        size_t base = r ? base1 : base0;

        float f0[4] = { xm[0]*c0.x + ym[0]*d0.x, xm[1]*c0.y + ym[1]*d0.y,
                        xm[2]*c0.z + ym[2]*d0.z, xm[3]*c0.w + ym[3]*d0.w };
        float f1[4] = { xm[0]*c1.x + ym[0]*d1.x, xm[1]*c1.y + ym[1]*d1.y,
                        xm[2]*c1.z + ym[2]*d1.z, xm[3]*c1.w + ym[3]*d1.w };
        float f2[4] = { xm[0]*c2.x + ym[0]*d2.x, xm[1]*c2.y + ym[1]*d2.y,
                        xm[2]*c2.z + ym[2]*d2.z, xm[3]*c2.w + ym[3]*d2.w };

        float4 o0, o1, o2;
        {
            float rr[4];
            #pragma unroll
            for (int j = 0; j < 4; j++) {
                float v = w00 * f0[j] + w01 * f1[j] + w02 * f2[j] + b0;
                rr[j] = v > 0.0f ? v : 0.0f;
            }
            o0 = make_float4(rr[0], rr[1], rr[2], rr[3]);
            #pragma unroll
            for (int j = 0; j < 4; j++) {
                float v = w10 * f0[j] + w11 * f1[j] + w12 * f2[j] + b1;
                rr[j] = v > 0.0f ? v : 0.0f;
            }
            o1 = make_float4(rr[0], rr[1], rr[2], rr[3]);
            #pragma unroll
            for (int j = 0; j < 4; j++) {
                float v = w20 * f0[j] + w21 * f1[j] + w22 * f2[j] + b2;
                rr[j] = v > 0.0f ? v : 0.0f;
            }
            o2 = make_float4(rr[0], rr[1], rr[2], rr[3]);
        }

        *(float4*)(out_main + base)             = o0;
        *(float4*)(out_main + base + plane)     = o1;
        *(float4*)(out_main + base + 2 * plane) = o2;

        size_t mbase = (size_t)b * plane + (size_t)(oy0 + r) * W2 + (size_t)ox4 * 4;
        *(float4*)(out_xm + mbase) = make_float4(xm[0], xm[1], xm[2], xm[3]);
        *(float4*)(out_ym + mbase) = make_float4(ym[0], ym[1], ym[2], ym[3]);
    }
}

extern "C" void kernel_launch(void* const* d_in, const int* in_sizes, int n_in,
                              void* d_out, int out_size) {
    const float* mask = (const float*)d_in[0];
    const float* xl   = (const float*)d_in[1];
    const float* yl   = (const float*)d_in[2];
    const float* cw   = (const float*)d_in[3];
    const float* cb   = (const float*)d_in[4];
    float* out = (float*)d_out;

    const int total = BB * HH * WV;          // 2,097,152 threads (2 rows each)
    const int threads = 256;
    const int blocks = (total + threads - 1) / threads;
    fused_upsample_blend_conv_kernel<<<blocks, threads>>>(mask, xl, yl, cw, cb, out);
}